// round 4
// baseline (speedup 1.0000x reference)
#include <cuda_runtime.h>
#include <cstdint>
#include <cstddef>

// Problem constants (fixed by setup_inputs)
#define NN 4
#define H0 60
#define W0 80
#define H1 60
#define W1 80
#define LL (H0*W0)     // 4800 rows
#define SS (H1*W1)     // 4800 cols
#define NL (NN*LL)
#define THRV 0.2f
#define BR 2

#define TPB 256
#define RPC 24                      // rows per CTA -> gridx 200
#define PARTS 3                     // column split per row
#define NQ (SS/4)                   // 1200 float4 per row
#define NQP (NQ/PARTS)              // 400 float4 per part
#define TAIL1 (NQP - TPB)           // 144: threads with a 2nd load

// Scratch (no allocations allowed). g_colmax zero at entry: module zero-init on
// first call, cleanup_kernel restores it at the end of every call.
__device__ unsigned g_colmax[NN*SS];       // colmax, u32 bit pattern (nonneg floats)
__device__ float    g_pmax[PARTS*NL];      // per-(part,row) max
__device__ int      g_pidx[PARTS*NL];      // per-(part,row) min index of max (global j)
__device__ int      g_pcnt[PARTS*NL];      // per-(part,row) count of max

__global__ void cleanup_kernel() {
    int i = blockIdx.x * blockDim.x + threadIdx.x;
    if (i < NN*SS) g_colmax[i] = 0u;
}

__global__ __launch_bounds__(TPB, 6) void pass1(const float4* __restrict__ conf) {
    const int part = blockIdx.y;
    const int n    = blockIdx.z;
    const int row0 = blockIdx.x * RPC;
    const int t    = threadIdx.x;
    const int warp = t >> 5, lane = t & 31;
    const bool tail = t < TAIL1;

    const float4* base = conf + ((size_t)n * LL + row0) * NQ + part * NQP + t;

    // colmax accumulators in integer domain (umax == fmax for nonneg floats)
    uint4 c0 = {0,0,0,0}, c1 = {0,0,0,0};

    __shared__ float s_max[RPC][8];
    __shared__ int   s_cnt[RPC][8];
    __shared__ int   s_idx[RPC][8];

#pragma unroll 4
    for (int r = 0; r < RPC; r++) {
        const float4* rp = base + (size_t)r * NQ;
        float4 a0 = __ldg(rp);
        float4 a1 = tail ? __ldg(rp + TPB) : make_float4(0.f,0.f,0.f,0.f);

        // column maxes (alu pipe)
        c0.x = umax(c0.x, __float_as_uint(a0.x)); c0.y = umax(c0.y, __float_as_uint(a0.y));
        c0.z = umax(c0.z, __float_as_uint(a0.z)); c0.w = umax(c0.w, __float_as_uint(a0.w));
        c1.x = umax(c1.x, __float_as_uint(a1.x)); c1.y = umax(c1.y, __float_as_uint(a1.y));
        c1.z = umax(c1.z, __float_as_uint(a1.z)); c1.w = umax(c1.w, __float_as_uint(a1.w));

        // thread-local part-row max (fma pipe)
        float tm = fmaxf(fmaxf(fmaxf(a0.x, a0.y), fmaxf(a0.z, a0.w)),
                         fmaxf(fmaxf(a1.x, a1.y), fmaxf(a1.z, a1.w)));

        // warp max via single REDUX on bit pattern
        float wm = __uint_as_float(__reduce_max_sync(0xffffffffu, __float_as_uint(tm)));

        // lazy (cnt, min-idx): on avg 1 lane/warp enters
        unsigned lcnt = 0u, lidx = 0x7fffffffu;
        if (tm == wm) {
            int j0 = (part*NQP + t) * 4;
            if (a0.x == wm) { lcnt++; lidx = min(lidx, (unsigned)(j0)); }
            if (a0.y == wm) { lcnt++; lidx = min(lidx, (unsigned)(j0+1)); }
            if (a0.z == wm) { lcnt++; lidx = min(lidx, (unsigned)(j0+2)); }
            if (a0.w == wm) { lcnt++; lidx = min(lidx, (unsigned)(j0+3)); }
            int j1 = j0 + 4*TPB;
            if (a1.x == wm) { lcnt++; lidx = min(lidx, (unsigned)(j1)); }
            if (a1.y == wm) { lcnt++; lidx = min(lidx, (unsigned)(j1+1)); }
            if (a1.z == wm) { lcnt++; lidx = min(lidx, (unsigned)(j1+2)); }
            if (a1.w == wm) { lcnt++; lidx = min(lidx, (unsigned)(j1+3)); }
        }
        unsigned wcnt = __reduce_add_sync(0xffffffffu, lcnt);
        unsigned widx = __reduce_min_sync(0xffffffffu, lidx);
        if (lane == 0) { s_max[r][warp] = wm; s_cnt[r][warp] = (int)wcnt; s_idx[r][warp] = (int)widx; }
    }
    __syncthreads();

    // combine 8 warp-partials per (part,row)
    if (t < RPC) {
        float m = -1.f; int c = 0, ix = 0;
#pragma unroll
        for (int w = 0; w < 8; w++) {
            float om = s_max[t][w];
            if (om > m)       { m = om; c = s_cnt[t][w]; ix = s_idx[t][w]; }
            else if (om == m) { c += s_cnt[t][w]; ix = min(ix, s_idx[t][w]); }
        }
        int gi = part * NL + n * LL + row0 + t;
        g_pmax[gi] = m; g_pidx[gi] = ix; g_pcnt[gi] = c;
    }

    // flush column-max partials (fire-and-forget RED.MAX)
    {
        unsigned* cm = &g_colmax[n * SS + (part*NQP + t) * 4];
        atomicMax(cm+0, c0.x); atomicMax(cm+1, c0.y); atomicMax(cm+2, c0.z); atomicMax(cm+3, c0.w);
        if (tail) {
            cm += 4*TPB;
            atomicMax(cm+0, c1.x); atomicMax(cm+1, c1.y); atomicMax(cm+2, c1.z); atomicMax(cm+3, c1.w);
        }
    }
}

__device__ __forceinline__ bool valid1(int j) {
    int r = j / W1, c = j % W1;
    return (r >= BR) & (r < H1 - BR) & (c >= BR) & (c < W1 - BR);
}

// thread-per-row fast path + CTA-cooperative rescan for the rare ambiguous rows
#define P2B 256
__global__ __launch_bounds__(P2B) void pass2(const float* __restrict__ conf,
                                             float* __restrict__ out) {
    __shared__ int   s_list[P2B];
    __shared__ float s_m[P2B];
    __shared__ int s_nl;
    __shared__ unsigned s_best;
    const int tid = threadIdx.x;
    const int gw  = blockIdx.x * P2B + tid;        // row id; grid exact: 75*256=19200
    if (tid == 0) s_nl = 0;
    __syncthreads();

    // merge the PARTS per-row partials
    float m = -1.f; int cnt = 0, jc = 0;
#pragma unroll
    for (int p = 0; p < PARTS; p++) {
        float om = g_pmax[p*NL + gw];
        int   oc = g_pcnt[p*NL + gw];
        int   oi = g_pidx[p*NL + gw];
        if (om > m)       { m = om; cnt = oc; jc = oi; }
        else if (om == m) { cnt += oc; jc = min(jc, oi); }
    }

    const int n = gw / LL, i = gw % LL;
    const int r0 = i / W0, c0 = i % W0;
    const bool v0 = (r0 >= BR) & (r0 < H0 - BR) & (c0 >= BR) & (c0 < W0 - BR);

    float mconf = 0.f; int jid = 0; float mv = 0.f;
    bool need = false;
    if (v0 && m > THRV) {
        // jc is the global min-index of the row max; if it passes the mask it is
        // the first True regardless of ties.
        if (valid1(jc) && g_colmax[n * SS + jc] == __float_as_uint(m)) {
            mv = 1.f; jid = jc; mconf = m;
        } else if (cnt > 1) {
            need = true;            // a later tied position may pass -> exact rescan
        }
    }
    if (need) { int p = atomicAdd(&s_nl, 1); s_list[p] = tid; s_m[tid] = m; }
    __syncthreads();
    if (!need) {
        out[gw]        = mconf;
        out[NL + gw]   = mv;
        out[2*NL + gw] = (float)jid;
    }

    const int nl = s_nl;
    for (int w = 0; w < nl; w++) {
        const int lrow = s_list[w];
        const int grow = blockIdx.x * P2B + lrow;
        const int nn = grow / LL, ii = grow % LL;
        const float mm = s_m[lrow];
        const float* rowp = conf + ((size_t)nn * LL + ii) * SS;
        if (tid == 0) s_best = 0x7fffffffu;
        __syncthreads();
        unsigned lb = 0x7fffffffu;
        for (int j = tid; j < SS; j += P2B) {
            float v = rowp[j];
            if (v == mm && valid1(j) && g_colmax[nn * SS + j] == __float_as_uint(v))
                lb = min(lb, (unsigned)j);
        }
        if (lb != 0x7fffffffu) atomicMin(&s_best, lb);
        __syncthreads();
        if (tid == 0) {
            unsigned b = s_best;
            bool hit = (b != 0x7fffffffu);
            out[grow]        = hit ? mm : 0.f;
            out[NL + grow]   = hit ? 1.f : 0.f;
            out[2*NL + grow] = hit ? (float)b : 0.f;
        }
        __syncthreads();
    }
}

extern "C" void kernel_launch(void* const* d_in, const int* in_sizes, int n_in,
                              void* d_out, int out_size) {
    const float* conf = (const float*)d_in[0];
    float* out = (float*)d_out;

    dim3 g1(LL / RPC, PARTS, NN);     // 200 x 3 x 4 = 2400 CTAs
    pass1<<<g1, TPB>>>((const float4*)conf);
    pass2<<<NL / P2B, P2B>>>(conf, out);          // 75 CTAs
    cleanup_kernel<<<(NN*SS + 255)/256, 256>>>();
}

// round 5
// speedup vs baseline: 1.3204x; 1.3204x over previous
#include <cuda_runtime.h>
#include <cstdint>
#include <cstddef>

// Problem constants (fixed by setup_inputs)
#define NN 4
#define H0 60
#define W0 80
#define H1 60
#define W1 80
#define LL (H0*W0)     // 4800 rows
#define SS (H1*W1)     // 4800 cols
#define NL (NN*LL)
#define THRV 0.2f
#define BR 2

#define TPB 256
#define NQ (SS/4)          // 1200 float4 per row
#define ROWB (SS*4)        // 19200 bytes per row
#define DEPTH 5            // pipeline stages
#define CTAS_PER_N 74      // 74*4 = 296 CTAs = exactly 2 per SM
#define MAXROWS 65         // ceil(4800/74)

// smem layout (dynamic)
#define SM_TILES 0                         // DEPTH * ROWB = 96000
#define SM_PMAX  (DEPTH*ROWB)              // 96000: MAXROWS*8 floats = 2080
#define SM_PCNT  (SM_PMAX + MAXROWS*8*4)   // 98080
#define SM_PIDX  (SM_PCNT + MAXROWS*8*4)   // 100160
#define SM_MBAR  (SM_PIDX + MAXROWS*8*4)   // 102240 (8-aligned)
#define SM_TOTAL (SM_MBAR + DEPTH*8 + 16)  // 102296 -> request 102400
#define SMEM_REQ 102400

// Scratch (no allocations allowed). g_colmax zero at entry: module zero-init on
// first call, cleanup_kernel restores it at the end of every call.
__device__ unsigned g_colmax[NN*SS];     // colmax as u32 bit pattern (nonneg floats)
__device__ float    g_rowmax[NL];
__device__ int      g_rowj[NL];          // min index achieving rowmax
__device__ int      g_rowcnt[NL];        // count of elements == rowmax

__global__ void cleanup_kernel() {
    int i = blockIdx.x * blockDim.x + threadIdx.x;
    if (i < NN*SS) g_colmax[i] = 0u;
}

__device__ __forceinline__ uint32_t smem_u32(const void* p) {
    uint32_t a;
    asm("{ .reg .u64 t; cvta.to.shared.u64 t, %1; cvt.u32.u64 %0, t; }" : "=r"(a) : "l"(p));
    return a;
}
__device__ __forceinline__ void mbar_init(uint32_t m, uint32_t cnt) {
    asm volatile("mbarrier.init.shared.b64 [%0], %1;" :: "r"(m), "r"(cnt) : "memory");
}
__device__ __forceinline__ void mbar_expect_tx(uint32_t m, uint32_t bytes) {
    asm volatile("mbarrier.arrive.expect_tx.shared.b64 _, [%0], %1;" :: "r"(m), "r"(bytes) : "memory");
}
__device__ __forceinline__ void bulk_ldg(uint32_t dst, const void* src, uint32_t bytes, uint32_t mbar) {
    asm volatile("cp.async.bulk.shared::cluster.global.mbarrier::complete_tx::bytes [%0], [%1], %2, [%3];"
                 :: "r"(dst), "l"(src), "r"(bytes), "r"(mbar) : "memory");
}
__device__ __forceinline__ void mbar_wait(uint32_t m, uint32_t ph) {
    uint32_t done;
    asm volatile("{\n\t.reg .pred p;\n\t"
                 "mbarrier.try_wait.parity.acquire.cta.shared::cta.b64 p, [%1], %2;\n\t"
                 "selp.b32 %0, 1, 0, p;\n\t}"
                 : "=r"(done) : "r"(m), "r"(ph) : "memory");
    if (!done) {
        asm volatile("{\n\t.reg .pred P1;\n\t"
                     "W_%=:\n\t"
                     "mbarrier.try_wait.parity.acquire.cta.shared::cta.b64 P1, [%0], %1, 0x989680;\n\t"
                     "@P1 bra.uni D_%=;\n\t"
                     "bra.uni W_%=;\n\t"
                     "D_%=:\n\t}"
                     :: "r"(m), "r"(ph) : "memory");
    }
}

__global__ __launch_bounds__(TPB) void pass1(const float* __restrict__ conf) {
    extern __shared__ __align__(16) unsigned char smem[];
    const int b = blockIdx.x;          // 0..73
    const int n = blockIdx.y;          // 0..3
    const int t = threadIdx.x;
    const int warp = t >> 5, lane = t & 31;
    const bool tail = t < (NQ - 4*TPB);   // t < 176

    const int rstart = (b * 4800) / CTAS_PER_N;
    const int rend   = ((b + 1) * 4800) / CTAS_PER_N;
    const int nrows  = rend - rstart;     // 64 or 65
    const size_t grow0 = (size_t)n * LL + rstart;

    float4* tiles = (float4*)(smem + SM_TILES);
    float*  spmax = (float*)(smem + SM_PMAX);
    int*    spcnt = (int*)(smem + SM_PCNT);
    int*    spidx = (int*)(smem + SM_PIDX);
    const uint32_t sbase = smem_u32(smem);
    const uint32_t mb0   = sbase + SM_MBAR;

    // init pipeline
    if (t == 0) {
        for (int s = 0; s < DEPTH; s++) mbar_init(mb0 + 8*s, 1);
        asm volatile("fence.proxy.async.shared::cta;" ::: "memory");
    }
    __syncthreads();
    if (t == 0) {
        for (int s = 0; s < DEPTH; s++) {
            mbar_expect_tx(mb0 + 8*s, ROWB);
            bulk_ldg(sbase + s*ROWB, (const char*)conf + (grow0 + s) * ROWB, ROWB, mb0 + 8*s);
        }
    }

    // colmax accumulators in integer domain (umax == fmax for nonneg floats)
    uint4 c0 = {0,0,0,0}, c1 = {0,0,0,0}, c2 = {0,0,0,0}, c3 = {0,0,0,0}, c4 = {0,0,0,0};

    int stage = 0, ph = 0;
    for (int r = 0; r < nrows; r++) {
        mbar_wait(mb0 + 8*stage, ph);

        const float4* tp = tiles + stage * NQ + t;
        float4 a0 = tp[0];
        float4 a1 = tp[TPB];
        float4 a2 = tp[2*TPB];
        float4 a3 = tp[3*TPB];
        float4 a4 = tail ? tp[4*TPB] : make_float4(0.f,0.f,0.f,0.f);

        c0.x = umax(c0.x, __float_as_uint(a0.x)); c0.y = umax(c0.y, __float_as_uint(a0.y));
        c0.z = umax(c0.z, __float_as_uint(a0.z)); c0.w = umax(c0.w, __float_as_uint(a0.w));
        c1.x = umax(c1.x, __float_as_uint(a1.x)); c1.y = umax(c1.y, __float_as_uint(a1.y));
        c1.z = umax(c1.z, __float_as_uint(a1.z)); c1.w = umax(c1.w, __float_as_uint(a1.w));
        c2.x = umax(c2.x, __float_as_uint(a2.x)); c2.y = umax(c2.y, __float_as_uint(a2.y));
        c2.z = umax(c2.z, __float_as_uint(a2.z)); c2.w = umax(c2.w, __float_as_uint(a2.w));
        c3.x = umax(c3.x, __float_as_uint(a3.x)); c3.y = umax(c3.y, __float_as_uint(a3.y));
        c3.z = umax(c3.z, __float_as_uint(a3.z)); c3.w = umax(c3.w, __float_as_uint(a3.w));
        c4.x = umax(c4.x, __float_as_uint(a4.x)); c4.y = umax(c4.y, __float_as_uint(a4.y));
        c4.z = umax(c4.z, __float_as_uint(a4.z)); c4.w = umax(c4.w, __float_as_uint(a4.w));

        float4 rm;
        rm.x = fmaxf(fmaxf(a0.x, a1.x), fmaxf(a2.x, a3.x)); rm.x = fmaxf(rm.x, a4.x);
        rm.y = fmaxf(fmaxf(a0.y, a1.y), fmaxf(a2.y, a3.y)); rm.y = fmaxf(rm.y, a4.y);
        rm.z = fmaxf(fmaxf(a0.z, a1.z), fmaxf(a2.z, a3.z)); rm.z = fmaxf(rm.z, a4.z);
        rm.w = fmaxf(fmaxf(a0.w, a1.w), fmaxf(a2.w, a3.w)); rm.w = fmaxf(rm.w, a4.w);
        float tm = fmaxf(fmaxf(rm.x, rm.y), fmaxf(rm.z, rm.w));

        float wm = __uint_as_float(__reduce_max_sync(0xffffffffu, __float_as_uint(tm)));

        unsigned lcnt = 0u, lidx = 0x7fffffffu;
        if (tm == wm) {
            int j0 = t * 4;
            if (a0.x == wm) { lcnt++; lidx = min(lidx, (unsigned)(j0)); }
            if (a0.y == wm) { lcnt++; lidx = min(lidx, (unsigned)(j0+1)); }
            if (a0.z == wm) { lcnt++; lidx = min(lidx, (unsigned)(j0+2)); }
            if (a0.w == wm) { lcnt++; lidx = min(lidx, (unsigned)(j0+3)); }
            int j1 = (t + TPB) * 4;
            if (a1.x == wm) { lcnt++; lidx = min(lidx, (unsigned)(j1)); }
            if (a1.y == wm) { lcnt++; lidx = min(lidx, (unsigned)(j1+1)); }
            if (a1.z == wm) { lcnt++; lidx = min(lidx, (unsigned)(j1+2)); }
            if (a1.w == wm) { lcnt++; lidx = min(lidx, (unsigned)(j1+3)); }
            int j2 = (t + 2*TPB) * 4;
            if (a2.x == wm) { lcnt++; lidx = min(lidx, (unsigned)(j2)); }
            if (a2.y == wm) { lcnt++; lidx = min(lidx, (unsigned)(j2+1)); }
            if (a2.z == wm) { lcnt++; lidx = min(lidx, (unsigned)(j2+2)); }
            if (a2.w == wm) { lcnt++; lidx = min(lidx, (unsigned)(j2+3)); }
            int j3 = (t + 3*TPB) * 4;
            if (a3.x == wm) { lcnt++; lidx = min(lidx, (unsigned)(j3)); }
            if (a3.y == wm) { lcnt++; lidx = min(lidx, (unsigned)(j3+1)); }
            if (a3.z == wm) { lcnt++; lidx = min(lidx, (unsigned)(j3+2)); }
            if (a3.w == wm) { lcnt++; lidx = min(lidx, (unsigned)(j3+3)); }
            int j4 = (t + 4*TPB) * 4;
            if (a4.x == wm) { lcnt++; lidx = min(lidx, (unsigned)(j4)); }
            if (a4.y == wm) { lcnt++; lidx = min(lidx, (unsigned)(j4+1)); }
            if (a4.z == wm) { lcnt++; lidx = min(lidx, (unsigned)(j4+2)); }
            if (a4.w == wm) { lcnt++; lidx = min(lidx, (unsigned)(j4+3)); }
        }
        unsigned wcnt = __reduce_add_sync(0xffffffffu, lcnt);
        unsigned widx = __reduce_min_sync(0xffffffffu, lidx);
        if (lane == 0) {
            spmax[r*8 + warp] = wm;
            spcnt[r*8 + warp] = (int)wcnt;
            spidx[r*8 + warp] = (int)widx;
        }

        __syncthreads();                 // everyone done reading tiles[stage]
        int rn = r + DEPTH;
        if (t == 0 && rn < nrows) {
            mbar_expect_tx(mb0 + 8*stage, ROWB);
            bulk_ldg(sbase + stage*ROWB, (const char*)conf + (grow0 + rn) * ROWB, ROWB, mb0 + 8*stage);
        }
        if (++stage == DEPTH) { stage = 0; ph ^= 1; }
    }
    __syncthreads();

    // combine 8 warp-partials per row
    if (t < nrows) {
        float m = -1.f; int c = 0, ix = 0;
#pragma unroll
        for (int w = 0; w < 8; w++) {
            float om = spmax[t*8 + w];
            if (om > m)       { m = om; c = spcnt[t*8 + w]; ix = spidx[t*8 + w]; }
            else if (om == m) { c += spcnt[t*8 + w]; ix = min(ix, spidx[t*8 + w]); }
        }
        size_t gi = grow0 + t;
        g_rowmax[gi] = m; g_rowj[gi] = ix; g_rowcnt[gi] = c;
    }

    // flush column-max partials (fire-and-forget RED.MAX)
    {
        unsigned* cm = &g_colmax[n * SS + 4*t];
        atomicMax(cm+0, c0.x); atomicMax(cm+1, c0.y); atomicMax(cm+2, c0.z); atomicMax(cm+3, c0.w);
        cm += 4*TPB;
        atomicMax(cm+0, c1.x); atomicMax(cm+1, c1.y); atomicMax(cm+2, c1.z); atomicMax(cm+3, c1.w);
        cm += 4*TPB;
        atomicMax(cm+0, c2.x); atomicMax(cm+1, c2.y); atomicMax(cm+2, c2.z); atomicMax(cm+3, c2.w);
        cm += 4*TPB;
        atomicMax(cm+0, c3.x); atomicMax(cm+1, c3.y); atomicMax(cm+2, c3.z); atomicMax(cm+3, c3.w);
        if (tail) {
            cm += 4*TPB;
            atomicMax(cm+0, c4.x); atomicMax(cm+1, c4.y); atomicMax(cm+2, c4.z); atomicMax(cm+3, c4.w);
        }
    }
}

__device__ __forceinline__ bool valid1(int j) {
    int r = j / W1, c = j % W1;
    return (r >= BR) & (r < H1 - BR) & (c >= BR) & (c < W1 - BR);
}

// thread-per-row fast path + CTA-cooperative rescan for the rare ambiguous rows
#define P2B 256
__global__ __launch_bounds__(P2B) void pass2(const float* __restrict__ conf,
                                             float* __restrict__ out) {
    __shared__ int   s_list[P2B];
    __shared__ float s_m[P2B];
    __shared__ int s_nl;
    __shared__ unsigned s_best;
    const int tid = threadIdx.x;
    const int gw  = blockIdx.x * P2B + tid;        // row id; grid exact: 75*256=19200
    if (tid == 0) s_nl = 0;
    __syncthreads();

    const int n = gw / LL, i = gw % LL;
    const float m  = g_rowmax[gw];
    const int cnt  = g_rowcnt[gw];
    const int jc   = g_rowj[gw];

    const int r0 = i / W0, c0 = i % W0;
    const bool v0 = (r0 >= BR) & (r0 < H0 - BR) & (c0 >= BR) & (c0 < W0 - BR);

    float mconf = 0.f; int jid = 0; float mv = 0.f;
    bool need = false;
    if (v0 && m > THRV) {
        // jc is the global min-index of the row max; if it passes the mask it is
        // the first True regardless of ties.
        if (valid1(jc) && g_colmax[n * SS + jc] == __float_as_uint(m)) {
            mv = 1.f; jid = jc; mconf = m;
        } else if (cnt > 1) {
            need = true;            // a later tied position may pass -> exact rescan
        }
    }
    if (need) { int p = atomicAdd(&s_nl, 1); s_list[p] = tid; s_m[tid] = m; }
    __syncthreads();
    if (!need) {
        out[gw]        = mconf;
        out[NL + gw]   = mv;
        out[2*NL + gw] = (float)jid;
    }

    const int nl = s_nl;
    for (int w = 0; w < nl; w++) {
        const int lrow = s_list[w];
        const int grow = blockIdx.x * P2B + lrow;
        const int nn = grow / LL, ii = grow % LL;
        const float mm = s_m[lrow];
        const float* rowp = conf + ((size_t)nn * LL + ii) * SS;
        if (tid == 0) s_best = 0x7fffffffu;
        __syncthreads();
        unsigned lb = 0x7fffffffu;
        for (int j = tid; j < SS; j += P2B) {
            float v = rowp[j];
            if (v == mm && valid1(j) && g_colmax[nn * SS + j] == __float_as_uint(v))
                lb = min(lb, (unsigned)j);
        }
        if (lb != 0x7fffffffu) atomicMin(&s_best, lb);
        __syncthreads();
        if (tid == 0) {
            unsigned b = s_best;
            bool hit = (b != 0x7fffffffu);
            out[grow]        = hit ? mm : 0.f;
            out[NL + grow]   = hit ? 1.f : 0.f;
            out[2*NL + grow] = hit ? (float)b : 0.f;
        }
        __syncthreads();
    }
}

extern "C" void kernel_launch(void* const* d_in, const int* in_sizes, int n_in,
                              void* d_out, int out_size) {
    const float* conf = (const float*)d_in[0];
    float* out = (float*)d_out;

    cudaFuncSetAttribute(pass1, cudaFuncAttributeMaxDynamicSharedMemorySize, SMEM_REQ);
    dim3 g1(CTAS_PER_N, NN);          // 74 x 4 = 296 CTAs = exactly 2 per SM
    pass1<<<g1, TPB, SMEM_REQ>>>(conf);
    pass2<<<NL / P2B, P2B>>>(conf, out);          // 75 CTAs
    cleanup_kernel<<<(NN*SS + 255)/256, 256>>>();
}